// round 16
// baseline (speedup 1.0000x reference)
#include <cuda_runtime.h>
#include <cuda_fp16.h>
#include <math.h>

#define S_TOK 8192
#define DM    1024
#define FFDIM 4096
#define NE    8
#define CAP   1280
#define NCHUNK 32                              // routing chunks of 256 tokens
#define SPLK2 4                                // GEMM2 split-K factor

#define BM 128
#define BN 128
#define BKH 64                                 // K halves per stage (128B row)
#define NSTG 3
#define A_STAGE_BYTES (BM * 128)               // 16384
#define STAGE_BYTES   (2 * A_STAGE_BYTES)      // 32768
#define SMEM_BYTES    (NSTG * STAGE_BYTES)     // 98304

// ---------------- scratch (device globals; no allocation allowed) ----------------
__device__ int    g_topk_i[S_TOK * 2];
__device__ float  g_topk_w[S_TOK * 2];
__device__ int    g_slot[S_TOK * 2];
__device__ int    g_lrank[S_TOK * 2];
__device__ int    g_ccnt[NCHUNK * NE];
__device__ int    g_coff[NCHUNK * NE];
__device__ int    g_idx[NE * CAP];
__device__ int    g_cnt[NE];
__device__ __half g_xh [(size_t)S_TOK * DM];        // fp16 x (token order, K-major)
__device__ __half g_w1h[(size_t)NE * FFDIM * DM];   // w1 -> [e][FF][DM] K-major fp16
__device__ __half g_w2h[(size_t)NE * DM * FFDIM];   // w2 -> [e][DM][FF] K-major fp16
__device__ __half g_h  [(size_t)NE * CAP * FFDIM];  // hidden fp16 (K-major for GEMM2)
__device__ __half g_outh[SPLK2][(size_t)NE * CAP * DM]; // expert output slices, fp16

__device__ __forceinline__ void mma_f16(float* d, const unsigned* a, const unsigned* b) {
    asm volatile(
        "mma.sync.aligned.m16n8k16.row.col.f32.f16.f16.f32 "
        "{%0,%1,%2,%3}, {%4,%5,%6,%7}, {%8,%9}, {%0,%1,%2,%3};\n"
        : "+f"(d[0]), "+f"(d[1]), "+f"(d[2]), "+f"(d[3])
        : "r"(a[0]), "r"(a[1]), "r"(a[2]), "r"(a[3]), "r"(b[0]), "r"(b[1]));
}

__device__ __forceinline__ void ldsm_x4(unsigned* r, unsigned addr) {
    asm volatile("ldmatrix.sync.aligned.m8n8.x4.shared.b16 {%0,%1,%2,%3}, [%4];"
                 : "=r"(r[0]), "=r"(r[1]), "=r"(r[2]), "=r"(r[3]) : "r"(addr));
}

// streaming 16B copy, L2-only (.cg)
__device__ __forceinline__ void cp_async16(unsigned smem_addr, const void* gptr, int src_bytes) {
    asm volatile("cp.async.cg.shared.global [%0], [%1], 16, %2;\n"
                 :: "r"(smem_addr), "l"(gptr), "r"(src_bytes));
}
__device__ __forceinline__ void cp_commit() { asm volatile("cp.async.commit_group;\n"); }
__device__ __forceinline__ void cp_wait1()  { asm volatile("cp.async.wait_group 1;\n"); }

// ---------------- fused: x -> fp16 conversion + gate logits + top2 ----------------
__global__ __launch_bounds__(256) void gatex_kernel(const float* __restrict__ x,
                                                    const float* __restrict__ gw,
                                                    const float* __restrict__ gb) {
    __shared__ float sgwt[NE * DM];
    int tid = threadIdx.x;
    for (int i = tid; i < DM * NE; i += 256) {
        int d = i >> 3, e = i & 7;
        sgwt[e * DM + d] = gw[i];
    }
    __syncthreads();

    int warp = tid >> 5, lane = tid & 31;
    int t = blockIdx.x * 8 + warp;
    const float* xr = x + (size_t)t * DM;
    __half2* xo = reinterpret_cast<__half2*>(g_xh + (size_t)t * DM);

    float acc[NE];
#pragma unroll
    for (int e = 0; e < NE; e++) acc[e] = 0.f;
#pragma unroll
    for (int d0 = 0; d0 < DM; d0 += 128) {
        int d = d0 + lane * 4;
        float4 xv = *reinterpret_cast<const float4*>(xr + d);
        xo[d >> 1]       = __floats2half2_rn(xv.x, xv.y);
        xo[(d >> 1) + 1] = __floats2half2_rn(xv.z, xv.w);
#pragma unroll
        for (int e = 0; e < NE; e++) {
            float4 gv = *reinterpret_cast<const float4*>(&sgwt[e * DM + d]);
            acc[e] += xv.x * gv.x + xv.y * gv.y + xv.z * gv.z + xv.w * gv.w;
        }
    }
#pragma unroll
    for (int e = 0; e < NE; e++) {
#pragma unroll
        for (int off = 16; off; off >>= 1)
            acc[e] += __shfl_xor_sync(0xffffffffu, acc[e], off);
    }
    if (lane == 0) {
        float l[NE];
#pragma unroll
        for (int e = 0; e < NE; e++) l[e] = acc[e] + gb[e];
        int i0 = 0;
#pragma unroll
        for (int e = 1; e < NE; e++) if (l[e] > l[i0]) i0 = e;
        int i1 = (i0 == 0) ? 1 : 0;
#pragma unroll
        for (int e = 0; e < NE; e++) if (e != i0 && l[e] > l[i1]) i1 = e;
        float p1 = expf(l[i1] - l[i0]);
        float w0 = 1.f / (1.f + p1);
        g_topk_i[2 * t] = i0; g_topk_i[2 * t + 1] = i1;
        g_topk_w[2 * t] = w0; g_topk_w[2 * t + 1] = 1.f - w0;
    }
}

// ---------------- transpose + convert weights: src[e][R][C] -> dst[e][C][R] fp16 ----------------
template<bool W1>
__global__ __launch_bounds__(256) void wtr_kernel(const float* __restrict__ src) {
    constexpr int R = W1 ? DM : FFDIM;
    constexpr int C = W1 ? FFDIM : DM;
    __half* dst = W1 ? g_w1h : g_w2h;
    __shared__ float b[32][65];                 // b[c][r]
    int e = blockIdx.z;
    int c0 = blockIdx.x * 32, r0 = blockIdx.y * 64;
    const float* s = src + (size_t)e * R * C;
    __half* d = dst + (size_t)e * R * C;
    int lane = threadIdx.x & 31, w = threadIdx.x >> 5;
#pragma unroll
    for (int i = 0; i < 8; i++) {
        int r = w * 8 + i;
        b[lane][r] = s[(size_t)(r0 + r) * C + c0 + lane];
    }
    __syncthreads();
#pragma unroll
    for (int i = 0; i < 4; i++) {
        int c = w + 8 * i;
        __half2 h = __floats2half2_rn(b[c][2 * lane], b[c][2 * lane + 1]);
        *reinterpret_cast<__half2*>(d + (size_t)(c0 + c) * R + r0 + 2 * lane) = h;
    }
}

// ---------------- routing (parallel, order-preserving) ----------------
__global__ __launch_bounds__(256) void routeA_kernel() {
    __shared__ int wsum[8];
    int tid = threadIdx.x, lane = tid & 31, warp = tid >> 5;
    int t = blockIdx.x * 256 + tid;
    int i0 = g_topk_i[2 * t], i1 = g_topk_i[2 * t + 1];
    int lr0 = 0, lr1 = 0;
    for (int e = 0; e < NE; e++) {
        int v = (i0 == e || i1 == e) ? 1 : 0;
#pragma unroll
        for (int off = 1; off < 32; off <<= 1) {
            int u = __shfl_up_sync(0xffffffffu, v, off);
            if (lane >= off) v += u;
        }
        if (lane == 31) wsum[warp] = v;
        __syncthreads();
        int woff = 0, total = 0;
#pragma unroll
        for (int w = 0; w < 8; w++) { int s = wsum[w]; total += s; if (w < warp) woff += s; }
        int lr = woff + v;
        if (i0 == e) lr0 = lr;
        if (i1 == e) lr1 = lr;
        if (tid == 0) g_ccnt[blockIdx.x * NE + e] = total;
        __syncthreads();
    }
    g_lrank[2 * t] = lr0; g_lrank[2 * t + 1] = lr1;
}

// warp-per-expert parallel scan over chunk counts
__global__ __launch_bounds__(256) void routeB_kernel() {
    int warp = threadIdx.x >> 5, lane = threadIdx.x & 31;   // warp = expert
    int v = g_ccnt[lane * NE + warp];
    int inc = v;
#pragma unroll
    for (int off = 1; off < 32; off <<= 1) {
        int u = __shfl_up_sync(0xffffffffu, inc, off);
        if (lane >= off) inc += u;
    }
    g_coff[lane * NE + warp] = inc - v;
    if (lane == 31) g_cnt[warp] = min(inc, CAP);
}

__global__ __launch_bounds__(256) void routeC_kernel() {
    int tid = threadIdx.x;
    int t = blockIdx.x * 256 + tid;
#pragma unroll
    for (int j = 0; j < 2; j++) {
        int e = g_topk_i[2 * t + j];
        int rank = g_coff[blockIdx.x * NE + e] + g_lrank[2 * t + j];
        int s = (rank <= CAP) ? rank - 1 : -1;
        g_slot[2 * t + j] = s;
        if (s >= 0) g_idx[e * CAP + s] = t;
    }
}

// ---------------- expert GEMM: 128 threads, warp tile 64x64 (2x2 warp grid) ----------------
// fp16 mma.sync m16n8k16 + ldmatrix + 3-stage cp.async. Per gr: 8 LDSM per 32 MMA (2x better
// LSU ratio than the 64x32 config). 2 CTAs/SM via high-reg 128-thread blocks.
// SPLITK>1: blockIdx.z = e*SPLITK + slice; fp16 partials to g_outh[slice] (bias only slice 0).
template<bool GATHER, bool RELU, int KDIM, int NDIM, int SPLITK>
__global__ __launch_bounds__(128, 2)
void gemm_kernel(const __half* __restrict__ Aglob,
                 const __half* __restrict__ Wglob,
                 const float* __restrict__ biasGlob) {
    extern __shared__ char smem[];
    __shared__ int sTok[BM];

    const int e = blockIdx.z / SPLITK;
    const int hlf = blockIdx.z % SPLITK;
    const int kOff = hlf * (KDIM / SPLITK);       // in halves
    const int rowBase = blockIdx.y * BM;
    const int nBase = blockIdx.x * BN;
    const int tid = threadIdx.x;

    const __half* Abase = GATHER ? Aglob : (g_h + (size_t)e * CAP * KDIM);
    const __half* W = Wglob + ((size_t)e * NDIM + nBase) * KDIM;
    const float* bias = biasGlob + e * NDIM;

    {
        int r = rowBase + tid;
        sTok[tid] = GATHER ? ((r < g_cnt[e]) ? g_idx[e * CAP + r] : -1) : r;
    }
    __syncthreads();

    const unsigned smem_base = (unsigned)__cvta_generic_to_shared(smem);

    // loader: 128 rows x 8 granules (16B) per operand; 128 threads -> 8+8 granules each
    const int ldRow0 = tid >> 2;          // 0..31, 4 passes of +32
    const int ldC0 = tid & 3;             // granules c and c+4

    auto load_stage = [&](int slot, int kk) {    // kk in halves (absolute)
        unsigned aB = smem_base + slot * STAGE_BYTES;
        unsigned bB = aB + A_STAGE_BYTES;
#pragma unroll
        for (int i = 0; i < 4; i++) {
            int row = ldRow0 + i * 32;
            int r7 = row & 7;
            int tok = sTok[row];
            const __half* asrc = Abase + (size_t)((tok < 0) ? 0 : tok) * KDIM + kk;
            const __half* bsrc = W + (size_t)row * KDIM + kk;
#pragma unroll
            for (int j = 0; j < 2; j++) {
                int c = ldC0 + j * 4;
                unsigned sw = (unsigned)(row * 128 + ((c ^ r7) << 4));
                cp_async16(aB + sw, asrc + c * 8, (tok >= 0) ? 16 : 0);
                cp_async16(bB + sw, bsrc + c * 8, 16);
            }
        }
    };

    float acc[4][8][4];
#pragma unroll
    for (int mt = 0; mt < 4; mt++)
#pragma unroll
        for (int nt = 0; nt < 8; nt++)
#pragma unroll
            for (int i = 0; i < 4; i++) acc[mt][nt][i] = 0.f;

    const int warp = tid >> 5, lane = tid & 31;
    const int wm = warp >> 1, wn = warp & 1;      // 2x2 grid, warp tile 64x64
    const int t4 = lane >> 3;
    const int row7 = lane & 7;

    const int aRowByte = (wm * 64 + (t4 & 1) * 8 + row7) * 128;
    const int aG = (t4 >> 1);
    const int bRowByte = (wn * 64 + (t4 >> 1) * 8 + row7) * 128;
    const int bG = (t4 & 1);

    const int NIT = (KDIM / SPLITK) / BKH;

    load_stage(0, kOff); cp_commit();
    load_stage(1, kOff + BKH); cp_commit();

    int slot = 0, nslot = 2;
    for (int k = 0; k < NIT; k++) {
        cp_wait1();
        __syncthreads();

        int nk = k + 2;
        if (nk < NIT) load_stage(nslot, kOff + nk * BKH);
        cp_commit();

        const unsigned sA = smem_base + slot * STAGE_BYTES;
        const unsigned sB = sA + A_STAGE_BYTES;

#pragma unroll
        for (int gr = 0; gr < 4; gr++) {
            unsigned a[4][4], b[8][2];
#pragma unroll
            for (int mt = 0; mt < 4; mt++)
                ldsm_x4(a[mt], sA + aRowByte + mt * 2048 + ((((2 * gr) + aG) ^ row7) << 4));
#pragma unroll
            for (int ntp = 0; ntp < 4; ntp++) {
                unsigned r[4];
                ldsm_x4(r, sB + bRowByte + ntp * 2048 + ((((2 * gr) + bG) ^ row7) << 4));
                b[2 * ntp][0] = r[0]; b[2 * ntp][1] = r[1];
                b[2 * ntp + 1][0] = r[2]; b[2 * ntp + 1][1] = r[3];
            }
#pragma unroll
            for (int mt = 0; mt < 4; mt++)
#pragma unroll
                for (int nt = 0; nt < 8; nt++)
                    mma_f16(acc[mt][nt], a[mt], b[nt]);
        }
        slot = (slot == NSTG - 1) ? 0 : slot + 1;
        nslot = (nslot == NSTG - 1) ? 0 : nslot + 1;
    }

    // epilogue (fp16 outputs for both paths)
    const int gid = lane >> 2, tig = lane & 3;
#pragma unroll
    for (int mt = 0; mt < 4; mt++) {
        int r0 = rowBase + wm * 64 + mt * 16 + gid;
#pragma unroll
        for (int nt = 0; nt < 8; nt++) {
            int c = nBase + wn * 64 + nt * 8 + 2 * tig;
            float bv0 = (hlf == 0) ? bias[c] : 0.f;
            float bv1 = (hlf == 0) ? bias[c + 1] : 0.f;
            float v00 = acc[mt][nt][0] + bv0;
            float v01 = acc[mt][nt][1] + bv1;
            float v10 = acc[mt][nt][2] + bv0;
            float v11 = acc[mt][nt][3] + bv1;
            if (RELU) {
                __half* OutH = g_h + (size_t)e * CAP * NDIM;
                *reinterpret_cast<__half2*>(OutH + (size_t)r0 * NDIM + c) =
                    __floats2half2_rn(fmaxf(v00, 0.f), fmaxf(v01, 0.f));
                *reinterpret_cast<__half2*>(OutH + (size_t)(r0 + 8) * NDIM + c) =
                    __floats2half2_rn(fmaxf(v10, 0.f), fmaxf(v11, 0.f));
            } else {
                __half* OutS = g_outh[hlf] + (size_t)e * CAP * NDIM;
                *reinterpret_cast<__half2*>(OutS + (size_t)r0 * NDIM + c) =
                    __floats2half2_rn(v00, v01);
                *reinterpret_cast<__half2*>(OutS + (size_t)(r0 + 8) * NDIM + c) =
                    __floats2half2_rn(v10, v11);
            }
        }
    }
}

// ---------------- combine (sums SPLK2 fp16 slices in fp32) ----------------
__global__ __launch_bounds__(256) void combine_kernel(float* __restrict__ out) {
    int t = blockIdx.x;
    int i0 = g_topk_i[2 * t], i1 = g_topk_i[2 * t + 1];
    int s0 = g_slot[2 * t], s1 = g_slot[2 * t + 1];
    float w0 = g_topk_w[2 * t], w1v = g_topk_w[2 * t + 1];
    int d = threadIdx.x * 4;
    float4 a = make_float4(0.f, 0.f, 0.f, 0.f);
#pragma unroll
    for (int j = 0; j < 2; j++) {
        int e = j ? i1 : i0;
        int s = j ? s1 : s0;
        float w = j ? w1v : w0;
        if (s < 0) continue;
        size_t off = ((size_t)e * CAP + s) * DM + d;
        float sx = 0.f, sy = 0.f, sz = 0.f, sw = 0.f;
#pragma unroll
        for (int sl = 0; sl < SPLK2; sl++) {
            const __half2* p = reinterpret_cast<const __half2*>(g_outh[sl] + off);
            float2 lo = __half22float2(p[0]);
            float2 hi = __half22float2(p[1]);
            sx += lo.x; sy += lo.y; sz += hi.x; sw += hi.y;
        }
        a.x += w * sx; a.y += w * sy; a.z += w * sz; a.w += w * sw;
    }
    *reinterpret_cast<float4*>(out + (size_t)t * DM + d) = a;
}

// ---------------- launch ----------------
extern "C" void kernel_launch(void* const* d_in, const int* in_sizes, int n_in,
                              void* d_out, int out_size) {
    (void)in_sizes; (void)n_in; (void)out_size;
    const float* x      = (const float*)d_in[0];
    const float* gate_w = (const float*)d_in[1];
    const float* gate_b = (const float*)d_in[2];
    const float* w1     = (const float*)d_in[3];
    const float* b1     = (const float*)d_in[4];
    const float* w2     = (const float*)d_in[5];
    const float* b2     = (const float*)d_in[6];
    float* out = (float*)d_out;

    static bool attr_done = false;
    if (!attr_done) {
        cudaFuncSetAttribute(gemm_kernel<true,  true,  DM,    FFDIM, 1>,
                             cudaFuncAttributeMaxDynamicSharedMemorySize, SMEM_BYTES);
        cudaFuncSetAttribute(gemm_kernel<false, false, FFDIM, DM,    SPLK2>,
                             cudaFuncAttributeMaxDynamicSharedMemorySize, SMEM_BYTES);
        attr_done = true;
    }

    static __half *p_xh = nullptr, *p_w1h = nullptr, *p_w2h = nullptr;
    if (!p_xh) {
        cudaGetSymbolAddress((void**)&p_xh,  g_xh);
        cudaGetSymbolAddress((void**)&p_w1h, g_w1h);
        cudaGetSymbolAddress((void**)&p_w2h, g_w2h);
    }

    gatex_kernel<<<S_TOK / 8, 256>>>(x, gate_w, gate_b);
    wtr_kernel<true ><<<dim3(FFDIM / 32, DM / 64, NE), 256>>>(w1);
    wtr_kernel<false><<<dim3(DM / 32, FFDIM / 64, NE), 256>>>(w2);

    routeA_kernel<<<NCHUNK, 256>>>();
    routeB_kernel<<<1, 256>>>();
    routeC_kernel<<<NCHUNK, 256>>>();

    gemm_kernel<true,  true,  DM,    FFDIM, 1>
        <<<dim3(FFDIM / BN, CAP / BM, NE), 128, SMEM_BYTES>>>(p_xh, p_w1h, b1);
    gemm_kernel<false, false, FFDIM, DM,    SPLK2>
        <<<dim3(DM / BN,    CAP / BM, NE * SPLK2), 128, SMEM_BYTES>>>(nullptr, p_w2h, b2);
    combine_kernel<<<S_TOK, 256>>>(out);
}

// round 17
// speedup vs baseline: 1.0149x; 1.0149x over previous
#include <cuda_runtime.h>
#include <cuda_fp16.h>
#include <math.h>

#define S_TOK 8192
#define DM    1024
#define FFDIM 4096
#define NE    8
#define CAP   1280
#define NCHUNK 32                              // routing chunks of 256 tokens
#define SPLK2 2                                // GEMM2 split-K factor (fp16 slices)

#define BM 128
#define BN 128
#define BKH 64                                 // K halves per stage (128B row)
#define NSTG 3
#define A_STAGE_BYTES (BM * 128)               // 16384
#define STAGE_BYTES   (2 * A_STAGE_BYTES)      // 32768
#define SMEM_BYTES    (NSTG * STAGE_BYTES)     // 98304

// ---------------- scratch (device globals; no allocation allowed) ----------------
__device__ int    g_topk_i[S_TOK * 2];
__device__ float  g_topk_w[S_TOK * 2];
__device__ int    g_slot[S_TOK * 2];
__device__ int    g_lrank[S_TOK * 2];
__device__ int    g_ccnt[NCHUNK * NE];
__device__ int    g_idx[NE * CAP];
__device__ int    g_cnt[NE];
__device__ __half g_xh [(size_t)S_TOK * DM];        // fp16 x (token order, K-major)
__device__ __half g_w1h[(size_t)NE * FFDIM * DM];   // w1 -> [e][FF][DM] K-major fp16
__device__ __half g_w2h[(size_t)NE * DM * FFDIM];   // w2 -> [e][DM][FF] K-major fp16
__device__ __half g_h  [(size_t)NE * CAP * FFDIM];  // hidden fp16 (K-major for GEMM2)
__device__ __half g_outh[SPLK2][(size_t)NE * CAP * DM]; // expert output slices, fp16

__device__ __forceinline__ void mma_f16(float* d, const unsigned* a, const unsigned* b) {
    asm volatile(
        "mma.sync.aligned.m16n8k16.row.col.f32.f16.f16.f32 "
        "{%0,%1,%2,%3}, {%4,%5,%6,%7}, {%8,%9}, {%0,%1,%2,%3};\n"
        : "+f"(d[0]), "+f"(d[1]), "+f"(d[2]), "+f"(d[3])
        : "r"(a[0]), "r"(a[1]), "r"(a[2]), "r"(a[3]), "r"(b[0]), "r"(b[1]));
}

__device__ __forceinline__ void ldsm_x4(unsigned* r, unsigned addr) {
    asm volatile("ldmatrix.sync.aligned.m8n8.x4.shared.b16 {%0,%1,%2,%3}, [%4];"
                 : "=r"(r[0]), "=r"(r[1]), "=r"(r[2]), "=r"(r[3]) : "r"(addr));
}

// streaming 16B copy, L2-only (.cg)
__device__ __forceinline__ void cp_async16(unsigned smem_addr, const void* gptr, int src_bytes) {
    asm volatile("cp.async.cg.shared.global [%0], [%1], 16, %2;\n"
                 :: "r"(smem_addr), "l"(gptr), "r"(src_bytes));
}
__device__ __forceinline__ void cp_commit() { asm volatile("cp.async.commit_group;\n"); }
__device__ __forceinline__ void cp_wait1()  { asm volatile("cp.async.wait_group 1;\n"); }

// ---------------- fused: x -> fp16 conversion + gate logits + top2 ----------------
__global__ __launch_bounds__(256) void gatex_kernel(const float* __restrict__ x,
                                                    const float* __restrict__ gw,
                                                    const float* __restrict__ gb) {
    __shared__ float sgwt[NE * DM];
    int tid = threadIdx.x;
    for (int i = tid; i < DM * NE; i += 256) {
        int d = i >> 3, e = i & 7;
        sgwt[e * DM + d] = gw[i];
    }
    __syncthreads();

    int warp = tid >> 5, lane = tid & 31;
    int t = blockIdx.x * 8 + warp;
    const float* xr = x + (size_t)t * DM;
    __half2* xo = reinterpret_cast<__half2*>(g_xh + (size_t)t * DM);

    float acc[NE];
#pragma unroll
    for (int e = 0; e < NE; e++) acc[e] = 0.f;
#pragma unroll
    for (int d0 = 0; d0 < DM; d0 += 128) {
        int d = d0 + lane * 4;
        float4 xv = *reinterpret_cast<const float4*>(xr + d);
        xo[d >> 1]       = __floats2half2_rn(xv.x, xv.y);
        xo[(d >> 1) + 1] = __floats2half2_rn(xv.z, xv.w);
#pragma unroll
        for (int e = 0; e < NE; e++) {
            float4 gv = *reinterpret_cast<const float4*>(&sgwt[e * DM + d]);
            acc[e] += xv.x * gv.x + xv.y * gv.y + xv.z * gv.z + xv.w * gv.w;
        }
    }
#pragma unroll
    for (int e = 0; e < NE; e++) {
#pragma unroll
        for (int off = 16; off; off >>= 1)
            acc[e] += __shfl_xor_sync(0xffffffffu, acc[e], off);
    }
    if (lane == 0) {
        float l[NE];
#pragma unroll
        for (int e = 0; e < NE; e++) l[e] = acc[e] + gb[e];
        int i0 = 0;
#pragma unroll
        for (int e = 1; e < NE; e++) if (l[e] > l[i0]) i0 = e;
        int i1 = (i0 == 0) ? 1 : 0;
#pragma unroll
        for (int e = 0; e < NE; e++) if (e != i0 && l[e] > l[i1]) i1 = e;
        float p1 = expf(l[i1] - l[i0]);
        float w0 = 1.f / (1.f + p1);
        g_topk_i[2 * t] = i0; g_topk_i[2 * t + 1] = i1;
        g_topk_w[2 * t] = w0; g_topk_w[2 * t + 1] = 1.f - w0;
    }
}

// ---------------- transpose + convert weights: src[e][R][C] -> dst[e][C][R] fp16 ----------------
template<bool W1>
__global__ __launch_bounds__(256) void wtr_kernel(const float* __restrict__ src) {
    constexpr int R = W1 ? DM : FFDIM;
    constexpr int C = W1 ? FFDIM : DM;
    __half* dst = W1 ? g_w1h : g_w2h;
    __shared__ float b[32][65];                 // b[c][r]
    int e = blockIdx.z;
    int c0 = blockIdx.x * 32, r0 = blockIdx.y * 64;
    const float* s = src + (size_t)e * R * C;
    __half* d = dst + (size_t)e * R * C;
    int lane = threadIdx.x & 31, w = threadIdx.x >> 5;
#pragma unroll
    for (int i = 0; i < 8; i++) {
        int r = w * 8 + i;
        b[lane][r] = s[(size_t)(r0 + r) * C + c0 + lane];
    }
    __syncthreads();
#pragma unroll
    for (int i = 0; i < 4; i++) {
        int c = w + 8 * i;
        __half2 h = __floats2half2_rn(b[c][2 * lane], b[c][2 * lane + 1]);
        *reinterpret_cast<__half2*>(d + (size_t)(c0 + c) * R + r0 + 2 * lane) = h;
    }
}

// ---------------- routing (parallel, order-preserving) ----------------
__global__ __launch_bounds__(256) void routeA_kernel() {
    __shared__ int wsum[8];
    int tid = threadIdx.x, lane = tid & 31, warp = tid >> 5;
    int t = blockIdx.x * 256 + tid;
    int i0 = g_topk_i[2 * t], i1 = g_topk_i[2 * t + 1];
    int lr0 = 0, lr1 = 0;
    for (int e = 0; e < NE; e++) {
        int v = (i0 == e || i1 == e) ? 1 : 0;
#pragma unroll
        for (int off = 1; off < 32; off <<= 1) {
            int u = __shfl_up_sync(0xffffffffu, v, off);
            if (lane >= off) v += u;
        }
        if (lane == 31) wsum[warp] = v;
        __syncthreads();
        int woff = 0, total = 0;
#pragma unroll
        for (int w = 0; w < 8; w++) { int s = wsum[w]; total += s; if (w < warp) woff += s; }
        int lr = woff + v;
        if (i0 == e) lr0 = lr;
        if (i1 == e) lr1 = lr;
        if (tid == 0) g_ccnt[blockIdx.x * NE + e] = total;
        __syncthreads();
    }
    g_lrank[2 * t] = lr0; g_lrank[2 * t + 1] = lr1;
}

// routeC with integrated chunk-offset scan (every block redundantly scans g_ccnt;
// all blocks write identical g_cnt values -> deterministic)
__global__ __launch_bounds__(256) void routeC_kernel() {
    __shared__ int scoff[NCHUNK * NE];
    int tid = threadIdx.x;
    {
        int warp = tid >> 5, lane = tid & 31;   // warp = expert, lane = chunk
        int v = g_ccnt[lane * NE + warp];
        int inc = v;
#pragma unroll
        for (int off = 1; off < 32; off <<= 1) {
            int u = __shfl_up_sync(0xffffffffu, inc, off);
            if (lane >= off) inc += u;
        }
        scoff[lane * NE + warp] = inc - v;      // exclusive prefix
        if (lane == 31) g_cnt[warp] = min(inc, CAP);
    }
    __syncthreads();

    int t = blockIdx.x * 256 + tid;
#pragma unroll
    for (int j = 0; j < 2; j++) {
        int e = g_topk_i[2 * t + j];
        int rank = scoff[blockIdx.x * NE + e] + g_lrank[2 * t + j];
        int s = (rank <= CAP) ? rank - 1 : -1;
        g_slot[2 * t + j] = s;
        if (s >= 0) g_idx[e * CAP + s] = t;
    }
}

// ---------------- expert GEMM: fp16 mma.sync m16n8k16 + ldmatrix + 3-stage cp.async ----------------
// 256 threads, 8 warps 2x4, warp tile 64x32 (the validated 553us configuration).
// SPLITK>1: blockIdx.z = e*SPLITK + slice; fp16 partials to g_outh[slice] (bias only slice 0).
template<bool GATHER, bool RELU, int KDIM, int NDIM, int SPLITK>
__global__ __launch_bounds__(256, 2)
void gemm_kernel(const __half* __restrict__ Aglob,
                 const __half* __restrict__ Wglob,
                 const float* __restrict__ biasGlob) {
    extern __shared__ char smem[];
    __shared__ int sTok[BM];

    const int e = blockIdx.z / SPLITK;
    const int hlf = blockIdx.z % SPLITK;
    const int kOff = hlf * (KDIM / SPLITK);       // in halves
    const int rowBase = blockIdx.y * BM;
    const int nBase = blockIdx.x * BN;
    const int tid = threadIdx.x;

    const __half* Abase = GATHER ? Aglob : (g_h + (size_t)e * CAP * KDIM);
    const __half* W = Wglob + ((size_t)e * NDIM + nBase) * KDIM;
    const float* bias = biasGlob + e * NDIM;

    if (tid < BM) {
        int r = rowBase + tid;
        sTok[tid] = GATHER ? ((r < g_cnt[e]) ? g_idx[e * CAP + r] : -1) : (rowBase + tid);
    }
    __syncthreads();

    const unsigned smem_base = (unsigned)__cvta_generic_to_shared(smem);

    const int ldRow0 = tid >> 2;
    const int ldC0 = tid & 3;

    auto load_stage = [&](int slot, int kk) {    // kk in halves (absolute)
        unsigned aB = smem_base + slot * STAGE_BYTES;
        unsigned bB = aB + A_STAGE_BYTES;
#pragma unroll
        for (int i = 0; i < 2; i++) {
            int row = ldRow0 + i * 64;
            int r7 = row & 7;
            int tok = sTok[row];
            const __half* asrc = Abase + (size_t)((tok < 0) ? 0 : tok) * KDIM + kk;
            const __half* bsrc = W + (size_t)row * KDIM + kk;
#pragma unroll
            for (int j = 0; j < 2; j++) {
                int c = ldC0 + j * 4;
                unsigned sw = (unsigned)(row * 128 + ((c ^ r7) << 4));
                cp_async16(aB + sw, asrc + c * 8, (tok >= 0) ? 16 : 0);
                cp_async16(bB + sw, bsrc + c * 8, 16);
            }
        }
    };

    float acc[4][4][4];
#pragma unroll
    for (int mt = 0; mt < 4; mt++)
#pragma unroll
        for (int nt = 0; nt < 4; nt++)
#pragma unroll
            for (int i = 0; i < 4; i++) acc[mt][nt][i] = 0.f;

    const int warp = tid >> 5, lane = tid & 31;
    const int wm = warp >> 2, wn = warp & 3;
    const int t4 = lane >> 3;
    const int row7 = lane & 7;

    const int aRowByte = (wm * 64 + (t4 & 1) * 8 + row7) * 128;
    const int aG = (t4 >> 1);
    const int bRowByte = (wn * 32 + (t4 >> 1) * 8 + row7) * 128;
    const int bG = (t4 & 1);

    const int NIT = (KDIM / SPLITK) / BKH;

    load_stage(0, kOff); cp_commit();
    load_stage(1, kOff + BKH); cp_commit();

    int slot = 0, nslot = 2;
    for (int k = 0; k < NIT; k++) {
        cp_wait1();
        __syncthreads();

        int nk = k + 2;
        if (nk < NIT) load_stage(nslot, kOff + nk * BKH);
        cp_commit();

        const unsigned sA = smem_base + slot * STAGE_BYTES;
        const unsigned sB = sA + A_STAGE_BYTES;

#pragma unroll
        for (int gr = 0; gr < 4; gr++) {
            unsigned a[4][4], b[4][2];
#pragma unroll
            for (int mt = 0; mt < 4; mt++)
                ldsm_x4(a[mt], sA + aRowByte + mt * 2048 + ((((2 * gr) + aG) ^ row7) << 4));
#pragma unroll
            for (int ntp = 0; ntp < 2; ntp++) {
                unsigned r[4];
                ldsm_x4(r, sB + bRowByte + ntp * 2048 + ((((2 * gr) + bG) ^ row7) << 4));
                b[2 * ntp][0] = r[0]; b[2 * ntp][1] = r[1];
                b[2 * ntp + 1][0] = r[2]; b[2 * ntp + 1][1] = r[3];
            }
#pragma unroll
            for (int mt = 0; mt < 4; mt++)
#pragma unroll
                for (int nt = 0; nt < 4; nt++)
                    mma_f16(acc[mt][nt], a[mt], b[nt]);
        }
        slot = (slot == NSTG - 1) ? 0 : slot + 1;
        nslot = (nslot == NSTG - 1) ? 0 : nslot + 1;
    }

    // epilogue (fp16 outputs for both paths)
    const int gid = lane >> 2, tig = lane & 3;
#pragma unroll
    for (int mt = 0; mt < 4; mt++) {
        int r0 = rowBase + wm * 64 + mt * 16 + gid;
#pragma unroll
        for (int nt = 0; nt < 4; nt++) {
            int c = nBase + wn * 32 + nt * 8 + 2 * tig;
            float bv0 = (hlf == 0) ? bias[c] : 0.f;
            float bv1 = (hlf == 0) ? bias[c + 1] : 0.f;
            float v00 = acc[mt][nt][0] + bv0;
            float v01 = acc[mt][nt][1] + bv1;
            float v10 = acc[mt][nt][2] + bv0;
            float v11 = acc[mt][nt][3] + bv1;
            if (RELU) {
                __half* OutH = g_h + (size_t)e * CAP * NDIM;
                *reinterpret_cast<__half2*>(OutH + (size_t)r0 * NDIM + c) =
                    __floats2half2_rn(fmaxf(v00, 0.f), fmaxf(v01, 0.f));
                *reinterpret_cast<__half2*>(OutH + (size_t)(r0 + 8) * NDIM + c) =
                    __floats2half2_rn(fmaxf(v10, 0.f), fmaxf(v11, 0.f));
            } else {
                __half* OutS = g_outh[hlf] + (size_t)e * CAP * NDIM;
                *reinterpret_cast<__half2*>(OutS + (size_t)r0 * NDIM + c) =
                    __floats2half2_rn(v00, v01);
                *reinterpret_cast<__half2*>(OutS + (size_t)(r0 + 8) * NDIM + c) =
                    __floats2half2_rn(v10, v11);
            }
        }
    }
}

// ---------------- combine (sums SPLK2 fp16 slices in fp32) ----------------
__global__ __launch_bounds__(256) void combine_kernel(float* __restrict__ out) {
    int t = blockIdx.x;
    int i0 = g_topk_i[2 * t], i1 = g_topk_i[2 * t + 1];
    int s0 = g_slot[2 * t], s1 = g_slot[2 * t + 1];
    float w0 = g_topk_w[2 * t], w1v = g_topk_w[2 * t + 1];
    int d = threadIdx.x * 4;
    float4 a = make_float4(0.f, 0.f, 0.f, 0.f);
#pragma unroll
    for (int j = 0; j < 2; j++) {
        int e = j ? i1 : i0;
        int s = j ? s1 : s0;
        float w = j ? w1v : w0;
        if (s < 0) continue;
        size_t off = ((size_t)e * CAP + s) * DM + d;
        float sx = 0.f, sy = 0.f, sz = 0.f, sw = 0.f;
#pragma unroll
        for (int sl = 0; sl < SPLK2; sl++) {
            const __half2* p = reinterpret_cast<const __half2*>(g_outh[sl] + off);
            float2 lo = __half22float2(p[0]);
            float2 hi = __half22float2(p[1]);
            sx += lo.x; sy += lo.y; sz += hi.x; sw += hi.y;
        }
        a.x += w * sx; a.y += w * sy; a.z += w * sz; a.w += w * sw;
    }
    *reinterpret_cast<float4*>(out + (size_t)t * DM + d) = a;
}

// ---------------- launch ----------------
extern "C" void kernel_launch(void* const* d_in, const int* in_sizes, int n_in,
                              void* d_out, int out_size) {
    (void)in_sizes; (void)n_in; (void)out_size;
    const float* x      = (const float*)d_in[0];
    const float* gate_w = (const float*)d_in[1];
    const float* gate_b = (const float*)d_in[2];
    const float* w1     = (const float*)d_in[3];
    const float* b1     = (const float*)d_in[4];
    const float* w2     = (const float*)d_in[5];
    const float* b2     = (const float*)d_in[6];
    float* out = (float*)d_out;

    static bool attr_done = false;
    if (!attr_done) {
        cudaFuncSetAttribute(gemm_kernel<true,  true,  DM,    FFDIM, 1>,
                             cudaFuncAttributeMaxDynamicSharedMemorySize, SMEM_BYTES);
        cudaFuncSetAttribute(gemm_kernel<false, false, FFDIM, DM,    SPLK2>,
                             cudaFuncAttributeMaxDynamicSharedMemorySize, SMEM_BYTES);
        attr_done = true;
    }

    static __half *p_xh = nullptr, *p_w1h = nullptr, *p_w2h = nullptr;
    if (!p_xh) {
        cudaGetSymbolAddress((void**)&p_xh,  g_xh);
        cudaGetSymbolAddress((void**)&p_w1h, g_w1h);
        cudaGetSymbolAddress((void**)&p_w2h, g_w2h);
    }

    gatex_kernel<<<S_TOK / 8, 256>>>(x, gate_w, gate_b);
    wtr_kernel<true ><<<dim3(FFDIM / 32, DM / 64, NE), 256>>>(w1);
    wtr_kernel<false><<<dim3(DM / 32, FFDIM / 64, NE), 256>>>(w2);

    routeA_kernel<<<NCHUNK, 256>>>();
    routeC_kernel<<<NCHUNK, 256>>>();

    gemm_kernel<true,  true,  DM,    FFDIM, 1>
        <<<dim3(FFDIM / BN, CAP / BM, NE), 256, SMEM_BYTES>>>(p_xh, p_w1h, b1);
    gemm_kernel<false, false, FFDIM, DM,    SPLK2>
        <<<dim3(DM / BN,    CAP / BM, NE * SPLK2), 256, SMEM_BYTES>>>(nullptr, p_w2h, b2);
    combine_kernel<<<S_TOK, 256>>>(out);
}